// round 6
// baseline (speedup 1.0000x reference)
#include <cuda_runtime.h>

#define Nn   10000
#define Ne   320000
#define EAt  330000      // edges + self loops
#define HID  256

typedef unsigned long long u64;

// ---------------- scratch (static device globals; zero-initialized at load) ------
__device__ float    g_loop[Nn];
__device__ int      g_cnt[Nn];
__device__ int      g_row[Nn+1];
__device__ int      g_woff[Nn];
__device__ int2     g_ced[EAt];      // (src, edge_attr bits) interleaved
__device__ float    g_xl[Nn*HID];
__device__ float    g_xr[Nn*HID];
__device__ float    g_h[Nn*HID];
__device__ float    g_pl[Nn*4];
__device__ float    g_red[2];

// ---------------- packed f32x2 helpers ----------------
__device__ __forceinline__ u64 add2(u64 a, u64 b){
    u64 r; asm("add.rn.f32x2 %0,%1,%2;" : "=l"(r) : "l"(a), "l"(b)); return r;
}
__device__ __forceinline__ u64 fma2(u64 a, u64 b, u64 c){
    u64 r; asm("fma.rn.f32x2 %0,%1,%2,%3;" : "=l"(r) : "l"(a), "l"(b), "l"(c)); return r;
}
__device__ __forceinline__ u64 bc2(float f){
    u64 r; asm("mov.b64 %0,{%1,%1};" : "=l"(r) : "f"(f)); return r;
}
__device__ __forceinline__ u64 pk2(float a, float b){
    u64 r; asm("mov.b64 %0,{%1,%2};" : "=l"(r) : "f"(a), "f"(b)); return r;
}
__device__ __forceinline__ float2 up2(u64 v){
    float2 r; asm("mov.b64 {%0,%1},%2;" : "=f"(r.x), "=f"(r.y) : "l"(v)); return r;
}
__device__ __forceinline__ u64 abs2(u64 v){ return v & 0x7FFFFFFF7FFFFFFFULL; }

// ---------------- kernel 1: edge histogram (+loop attr sum)  ||  lin1 ----------------
#define HB 1250   // (Ne+255)/256
__global__ void k_hist_lin1(const int* __restrict__ dst, const float* __restrict__ ea,
                            const float* __restrict__ x,
                            const float* __restrict__ Wl, const float* __restrict__ bl,
                            const float* __restrict__ Wr, const float* __restrict__ br){
    int b = blockIdx.x;
    if(b < HB){
        int e = b*256 + threadIdx.x;
        if(e < Ne){
            int d = dst[e];
            atomicAdd(&g_cnt[d], 1);
            atomicAdd(&g_loop[d], ea[e]);
        }
    } else {
        int t = (b - HB)*256 + threadIdx.x;
        if(t < Nn*64){
            int n = t >> 6, c4 = (t & 63) << 2;
            float4 xv = *(const float4*)(x + n*4);
            float4 l = *(const float4*)(bl + c4);
            float4 r = *(const float4*)(br + c4);
            float4 w;
            w = *(const float4*)(Wl + 0*256 + c4); l.x+=xv.x*w.x; l.y+=xv.x*w.y; l.z+=xv.x*w.z; l.w+=xv.x*w.w;
            w = *(const float4*)(Wl + 1*256 + c4); l.x+=xv.y*w.x; l.y+=xv.y*w.y; l.z+=xv.y*w.z; l.w+=xv.y*w.w;
            w = *(const float4*)(Wl + 2*256 + c4); l.x+=xv.z*w.x; l.y+=xv.z*w.y; l.z+=xv.z*w.z; l.w+=xv.z*w.w;
            w = *(const float4*)(Wl + 3*256 + c4); l.x+=xv.w*w.x; l.y+=xv.w*w.y; l.z+=xv.w*w.z; l.w+=xv.w*w.w;
            w = *(const float4*)(Wr + 0*256 + c4); r.x+=xv.x*w.x; r.y+=xv.x*w.y; r.z+=xv.x*w.z; r.w+=xv.x*w.w;
            w = *(const float4*)(Wr + 1*256 + c4); r.x+=xv.y*w.x; r.y+=xv.y*w.y; r.z+=xv.y*w.z; r.w+=xv.y*w.w;
            w = *(const float4*)(Wr + 2*256 + c4); r.x+=xv.z*w.x; r.y+=xv.z*w.y; r.z+=xv.z*w.z; r.w+=xv.z*w.w;
            w = *(const float4*)(Wr + 3*256 + c4); r.x+=xv.w*w.x; r.y+=xv.w*w.y; r.z+=xv.w*w.z; r.w+=xv.w*w.w;
            *(float4*)(g_xl + n*256 + c4) = l;
            *(float4*)(g_xr + n*256 + c4) = r;
        }
    }
}

// ---------------- kernel 2: scan + prep (single block) ----------------
__global__ void k_scanprep(){
    __shared__ int part[1024];
    const int NP = 10;
    int tid = threadIdx.x;
    int base = tid * NP;
    int cnt[NP], loc[NP];
    int s = 0;
    #pragma unroll
    for(int i = 0; i < NP; i++){
        int idx = base + i;
        int c = (idx < Nn) ? g_cnt[idx] : 0;
        cnt[i] = c;
        loc[i] = s;
        s += (idx < Nn) ? (c + 1) : 0;
    }
    part[tid] = s; __syncthreads();
    for(int o = 1; o < 1024; o <<= 1){
        int v = (tid >= o) ? part[tid - o] : 0;
        __syncthreads();
        if(tid >= o) part[tid] += v;
        __syncthreads();
    }
    int off = (tid > 0) ? part[tid - 1] : 0;
    #pragma unroll
    for(int i = 0; i < NP; i++){
        int idx = base + i;
        if(idx < Nn){
            int rs = off + loc[i];
            int re = rs + cnt[i] + 1;
            g_row[idx] = rs;
            if(idx == Nn-1) g_row[Nn] = re;
            float lp = g_loop[idx] / fmaxf((float)cnt[i], 1.f);
            g_ced[re-1] = make_int2(idx, __float_as_int(lp));
            g_woff[idx] = rs;
        }
    }
}

// ---------------- kernel 3: scatter edges into CSR ----------------
__global__ void k_scatter(const int* __restrict__ src, const int* __restrict__ dst,
                          const float* __restrict__ ea){
    int e = blockIdx.x*blockDim.x + threadIdx.x;
    if(e >= Ne) return;
    int d = dst[e];
    int pos = atomicAdd(&g_woff[d], 1);
    g_ced[pos] = make_int2(src[e], __float_as_int(ea[e]));
}

// ---------------- fused conv (both layers): packed-f32x2 edge loop ----------------
// att·lrelu(z) = (0.6att)·z + (0.4att)·|z|  (exact reformulation)
// NSH = shuffle levels: 3 for conv1 (heads of 64ch), 5 for conv2 (256ch)
template<int NSH>
__global__ void k_conv(const float* __restrict__ We, const float* __restrict__ att,
                       const float* __restrict__ bias, const float* __restrict__ gam,
                       const float* __restrict__ bet){
    int n = (blockIdx.x*blockDim.x + threadIdx.x) >> 5;
    int lane = threadIdx.x & 31;
    if(n >= Nn) return;
    int c0 = lane * 8;
    const ulonglong2* prp = (const ulonglong2*)(g_xr + n*HID + c0);
    ulonglong2 rA = prp[0], rB = prp[1];
    u64 r_p[4] = {rA.x, rA.y, rB.x, rB.y};
    const ulonglong2* pwp = (const ulonglong2*)(We + c0);
    ulonglong2 wA = pwp[0], wB = pwp[1];
    u64 w_p[4] = {wA.x, wA.y, wB.x, wB.y};
    float4 t0 = *(const float4*)(att + c0), t1 = *(const float4*)(att + c0 + 4);
    float tv[8] = {t0.x,t0.y,t0.z,t0.w,t1.x,t1.y,t1.z,t1.w};
    u64 a06[4], a04[4];
    #pragma unroll
    for(int j = 0; j < 4; j++){
        a06[j] = pk2(0.6f*tv[2*j], 0.6f*tv[2*j+1]);
        a04[j] = pk2(0.4f*tv[2*j], 0.4f*tv[2*j+1]);
    }
    u64 acc[4] = {0ULL,0ULL,0ULL,0ULL};
    float den = 0.f;
    int b = g_row[n], e = g_row[n+1];
    int i = b;
    for(; i + 1 < e; i += 2){
        int2 ed0 = g_ced[i], ed1 = g_ced[i+1];
        const ulonglong2* pA = (const ulonglong2*)(g_xl + ed0.x*HID + c0);
        const ulonglong2* pB = (const ulonglong2*)(g_xl + ed1.x*HID + c0);
        ulonglong2 lA0 = pA[0], lA1 = pA[1];
        ulonglong2 lB0 = pB[0], lB1 = pB[1];
        u64 la[4] = {lA0.x, lA0.y, lA1.x, lA1.y};
        u64 lb[4] = {lB0.x, lB0.y, lB1.x, lB1.y};
        u64 ev0 = bc2(__int_as_float(ed0.y));
        u64 ev1 = bc2(__int_as_float(ed1.y));
        u64 pa0 = 0ULL, pa1 = 0ULL, pb0 = 0ULL, pb1 = 0ULL;
        #pragma unroll
        for(int j = 0; j < 4; j++){
            u64 z0 = fma2(ev0, w_p[j], add2(la[j], r_p[j]));
            u64 z1 = fma2(ev1, w_p[j], add2(lb[j], r_p[j]));
            pa0 = fma2(z0, a06[j], pa0);
            pa1 = fma2(abs2(z0), a04[j], pa1);
            pb0 = fma2(z1, a06[j], pb0);
            pb1 = fma2(abs2(z1), a04[j], pb1);
        }
        float2 f0 = up2(add2(pa0, pa1));
        float2 f1 = up2(add2(pb0, pb1));
        float p0 = f0.x + f0.y;
        float p1 = f1.x + f1.y;
        #pragma unroll
        for(int o = 0; o < NSH; o++){
            p0 += __shfl_xor_sync(0xffffffffu, p0, 1 << o);
            p1 += __shfl_xor_sync(0xffffffffu, p1, 1 << o);
        }
        float e0 = __expf(p0);
        float e1 = __expf(p1);
        den += e0 + e1;
        u64 eb0 = bc2(e0), eb1 = bc2(e1);
        #pragma unroll
        for(int j = 0; j < 4; j++){
            acc[j] = fma2(la[j], eb0, acc[j]);
            acc[j] = fma2(lb[j], eb1, acc[j]);
        }
    }
    if(i < e){
        int2 ed0 = g_ced[i];
        const ulonglong2* pA = (const ulonglong2*)(g_xl + ed0.x*HID + c0);
        ulonglong2 lA0 = pA[0], lA1 = pA[1];
        u64 la[4] = {lA0.x, lA0.y, lA1.x, lA1.y};
        u64 ev0 = bc2(__int_as_float(ed0.y));
        u64 pa0 = 0ULL, pa1 = 0ULL;
        #pragma unroll
        for(int j = 0; j < 4; j++){
            u64 z0 = fma2(ev0, w_p[j], add2(la[j], r_p[j]));
            pa0 = fma2(z0, a06[j], pa0);
            pa1 = fma2(abs2(z0), a04[j], pa1);
        }
        float2 f0 = up2(add2(pa0, pa1));
        float p0 = f0.x + f0.y;
        #pragma unroll
        for(int o = 0; o < NSH; o++)
            p0 += __shfl_xor_sync(0xffffffffu, p0, 1 << o);
        float e0 = __expf(p0);
        den += e0;
        u64 eb0 = bc2(e0);
        #pragma unroll
        for(int j = 0; j < 4; j++)
            acc[j] = fma2(la[j], eb0, acc[j]);
    }
    // epilogue: normalize + bias + LayerNorm + ReLU
    float inv = 1.f / den;
    float v[8];
    #pragma unroll
    for(int j = 0; j < 4; j++){
        float2 a2 = up2(acc[j]);
        v[2*j]   = a2.x;
        v[2*j+1] = a2.y;
    }
    float s = 0.f;
    #pragma unroll
    for(int k = 0; k < 8; k++){ v[k] = v[k]*inv + bias[c0+k]; s += v[k]; }
    #pragma unroll
    for(int o = 16; o; o >>= 1) s += __shfl_xor_sync(0xffffffffu, s, o);
    float mu = s * (1.f/256.f);
    float q = 0.f;
    #pragma unroll
    for(int k = 0; k < 8; k++){ float dd = v[k]-mu; q += dd*dd; }
    #pragma unroll
    for(int o = 16; o; o >>= 1) q += __shfl_xor_sync(0xffffffffu, q, o);
    float rstd = rsqrtf(q*(1.f/256.f) + 1e-5f);
    float o0[8];
    #pragma unroll
    for(int k = 0; k < 8; k++)
        o0[k] = fmaxf((v[k]-mu)*rstd*gam[c0+k] + bet[c0+k], 0.f);
    *(float4*)(g_h + n*HID + c0)     = make_float4(o0[0],o0[1],o0[2],o0[3]);
    *(float4*)(g_h + n*HID + c0 + 4) = make_float4(o0[4],o0[5],o0[6],o0[7]);
}

// ---------------- dual GEMM (proven 64x64 fp32 tile), one launch ----------------
__global__ void k_gemm_dual(const float* __restrict__ Wl, const float* __restrict__ bl,
                            const float* __restrict__ Wr, const float* __restrict__ br){
    __shared__ __align__(16) float As[16][68];
    __shared__ __align__(16) float Bs[16][68];
    int half = blockIdx.x >> 2;
    int nblk = blockIdx.x & 3;
    const float* B    = half ? Wr   : Wl;
    const float* bias = half ? br   : bl;
    float*       C    = half ? g_xr : g_xl;
    int m0 = blockIdx.y*64, n0 = nblk*64;
    int t = threadIdx.x;
    int tx = t & 15, ty = t >> 4;
    float acc[4][4] = {};
    int arow = t >> 2, ak = (t & 3) * 4;
    int brow = t >> 4, bc = (t & 15) * 4;
    for(int k0 = 0; k0 < 256; k0 += 16){
        float4 av = make_float4(0.f,0.f,0.f,0.f);
        int gm = m0 + arow;
        if(gm < Nn) av = *(const float4*)(g_h + gm*256 + k0 + ak);
        As[ak+0][arow] = av.x; As[ak+1][arow] = av.y;
        As[ak+2][arow] = av.z; As[ak+3][arow] = av.w;
        *(float4*)&Bs[brow][bc] = *(const float4*)(B + (k0+brow)*256 + n0 + bc);
        __syncthreads();
        #pragma unroll
        for(int kk = 0; kk < 16; kk++){
            float4 a = *(float4*)&As[kk][ty*4];
            float4 b = *(float4*)&Bs[kk][tx*4];
            acc[0][0]+=a.x*b.x; acc[0][1]+=a.x*b.y; acc[0][2]+=a.x*b.z; acc[0][3]+=a.x*b.w;
            acc[1][0]+=a.y*b.x; acc[1][1]+=a.y*b.y; acc[1][2]+=a.y*b.z; acc[1][3]+=a.y*b.w;
            acc[2][0]+=a.z*b.x; acc[2][1]+=a.z*b.y; acc[2][2]+=a.z*b.z; acc[2][3]+=a.z*b.w;
            acc[3][0]+=a.w*b.x; acc[3][1]+=a.w*b.y; acc[3][2]+=a.w*b.z; acc[3][3]+=a.w*b.w;
        }
        __syncthreads();
    }
    #pragma unroll
    for(int i = 0; i < 4; i++){
        int gm = m0 + ty*4 + i;
        if(gm >= Nn) continue;
        #pragma unroll
        for(int j = 0; j < 4; j++){
            int col = n0 + tx*4 + j;
            C[gm*256 + col] = acc[i][j] + bias[col];
        }
    }
}

// ---------------- policy GEMM (fp32 mainloop) + fused final projection ----------
__global__ void k_gemm_pol(const float* __restrict__ Wp1, const float* __restrict__ bp1,
                           const float* __restrict__ Wp2, const float* __restrict__ bp2){
    __shared__ __align__(16) float As[16][68];
    __shared__ __align__(16) float Bs[16][132];
    int m0 = blockIdx.x * 64;
    int t = threadIdx.x;
    int tx = t & 15, ty = t >> 4;
    int ar = t >> 2, ak = (t & 3) * 4;
    int br_ = t >> 4, bc = (t & 15) * 8;
    float acc[4][8] = {};
    for(int k0 = 0; k0 < 256; k0 += 16){
        float4 av = make_float4(0.f,0.f,0.f,0.f);
        int gm = m0 + ar;
        if(gm < Nn) av = *(const float4*)(g_h + gm*256 + k0 + ak);
        As[ak+0][ar] = av.x; As[ak+1][ar] = av.y;
        As[ak+2][ar] = av.z; As[ak+3][ar] = av.w;
        *(float4*)&Bs[br_][bc]   = *(const float4*)(Wp1 + (k0+br_)*128 + bc);
        *(float4*)&Bs[br_][bc+4] = *(const float4*)(Wp1 + (k0+br_)*128 + bc + 4);
        __syncthreads();
        #pragma unroll
        for(int kk = 0; kk < 16; kk++){
            float4 a = *(float4*)&As[kk][ty*4];
            float4 b0 = *(float4*)&Bs[kk][tx*8];
            float4 b1 = *(float4*)&Bs[kk][tx*8+4];
            float av4[4] = {a.x,a.y,a.z,a.w};
            float bv[8] = {b0.x,b0.y,b0.z,b0.w,b1.x,b1.y,b1.z,b1.w};
            #pragma unroll
            for(int i = 0; i < 4; i++)
                #pragma unroll
                for(int j = 0; j < 8; j++)
                    acc[i][j] += av4[i]*bv[j];
        }
        __syncthreads();
    }
    float4 bpA = *(const float4*)(bp1 + tx*8);
    float4 bpB = *(const float4*)(bp1 + tx*8 + 4);
    float bb[8] = {bpA.x,bpA.y,bpA.z,bpA.w,bpB.x,bpB.y,bpB.z,bpB.w};
    float4 wv[8];
    const float4* wp = (const float4*)(Wp2 + tx*32);
    #pragma unroll
    for(int j = 0; j < 8; j++) wv[j] = wp[j];
    float part[4][4];
    #pragma unroll
    for(int i = 0; i < 4; i++){
        part[i][0] = part[i][1] = part[i][2] = part[i][3] = 0.f;
        bool ok = (m0 + ty*4 + i) < Nn;
        #pragma unroll
        for(int j = 0; j < 8; j++){
            float v0 = ok ? fmaxf(acc[i][j] + bb[j], 0.f) : 0.f;
            part[i][0] += v0*wv[j].x;
            part[i][1] += v0*wv[j].y;
            part[i][2] += v0*wv[j].z;
            part[i][3] += v0*wv[j].w;
        }
    }
    #pragma unroll
    for(int i = 0; i < 4; i++)
        #pragma unroll
        for(int c = 0; c < 4; c++){
            #pragma unroll
            for(int o = 1; o < 16; o <<= 1)
                part[i][c] += __shfl_xor_sync(0xffffffffu, part[i][c], o);
        }
    if(tx == 0){
        #pragma unroll
        for(int i = 0; i < 4; i++){
            int gm = m0 + ty*4 + i;
            if(gm < Nn){
                float4 r4 = make_float4(part[i][0]+bp2[0], part[i][1]+bp2[1],
                                        part[i][2]+bp2[2], part[i][3]+bp2[3]);
                *(float4*)(g_pl + gm*4) = r4;
            }
        }
    }
}

// ---------------- global softmax (40000 logits) ----------------
__global__ void k_reduce(){
    __shared__ float sm[1024];
    int tid = threadIdx.x;
    float m = -3.4e38f;
    for(int i = tid; i < Nn*4; i += 1024) m = fmaxf(m, g_pl[i]);
    sm[tid] = m; __syncthreads();
    for(int o = 512; o > 0; o >>= 1){ if(tid < o) sm[tid] = fmaxf(sm[tid], sm[tid+o]); __syncthreads(); }
    float mx = sm[0]; __syncthreads();
    float s = 0.f;
    for(int i = tid; i < Nn*4; i += 1024) s += expf(g_pl[i] - mx);
    sm[tid] = s; __syncthreads();
    for(int o = 512; o > 0; o >>= 1){ if(tid < o) sm[tid] += sm[tid+o]; __syncthreads(); }
    if(tid == 0){ g_red[0] = mx; g_red[1] = sm[0]; }
}
// output + restore g_cnt/g_loop to zero for the next graph replay
__global__ void k_out(float* __restrict__ out){
    int i = blockIdx.x*blockDim.x + threadIdx.x;
    if(i < Nn*4) out[i] = expf(g_pl[i] - g_red[0]) / g_red[1];
    if(i < Nn){ g_cnt[i] = 0; g_loop[i] = 0.f; }
}

// ---------------- launch ----------------
extern "C" void kernel_launch(void* const* d_in, const int* in_sizes, int n_in,
                              void* d_out, int out_size){
    const float* x     = (const float*)d_in[0];
    const int*   ei    = (const int*)  d_in[1];
    const float* ea    = (const float*)d_in[2];
    const float* Wl1   = (const float*)d_in[3];
    const float* bl1   = (const float*)d_in[4];
    const float* Wr1   = (const float*)d_in[5];
    const float* br1   = (const float*)d_in[6];
    const float* We1   = (const float*)d_in[7];
    const float* att1  = (const float*)d_in[8];
    const float* bias1 = (const float*)d_in[9];
    const float* g1    = (const float*)d_in[10];
    const float* be1   = (const float*)d_in[11];
    const float* Wl2   = (const float*)d_in[12];
    const float* bl2   = (const float*)d_in[13];
    const float* Wr2   = (const float*)d_in[14];
    const float* br2   = (const float*)d_in[15];
    const float* We2   = (const float*)d_in[16];
    const float* att2  = (const float*)d_in[17];
    const float* bias2 = (const float*)d_in[18];
    const float* g2    = (const float*)d_in[19];
    const float* be2   = (const float*)d_in[20];
    const float* Wp1   = (const float*)d_in[21];
    const float* bp1   = (const float*)d_in[22];
    const float* Wp2   = (const float*)d_in[23];
    const float* bp2   = (const float*)d_in[24];
    const int* src = ei;
    const int* dst = ei + Ne;
    float* out = (float*)d_out;

    const int TB = 256;

    // CSR build + conv1 linear (merged)
    k_hist_lin1<<<HB + (Nn*64+TB-1)/TB, TB>>>(dst, ea, x, Wl1, bl1, Wr1, br1);
    k_scanprep<<<1, 1024>>>();
    k_scatter<<<(Ne+TB-1)/TB, TB>>>(src, dst, ea);

    // conv1 (heads=4: reduce over 8 lanes -> 3 shuffle levels)
    k_conv<3><<<(Nn*32+TB-1)/TB, TB>>>(We1, att1, bias1, g1, be1);

    // conv2
    k_gemm_dual<<<dim3(8, (Nn+63)/64), 256>>>(Wl2, bl2, Wr2, br2);
    k_conv<5><<<(Nn*32+TB-1)/TB, TB>>>(We2, att2, bias2, g2, be2);

    // policy head (fused final projection)
    k_gemm_pol<<<(Nn+63)/64, 256>>>(Wp1, bp1, Wp2, bp2);

    // global softmax
    k_reduce<<<1, 1024>>>();
    k_out<<<(Nn*4+TB-1)/TB, TB>>>(out);
}

// round 7
// speedup vs baseline: 1.0774x; 1.0774x over previous
#include <cuda_runtime.h>

#define Nn   10000
#define Ne   320000
#define EAt  330000      // edges + self loops
#define HID  256
#define NRED 20          // partial-reduction blocks for final softmax

// ---------------- scratch (static device globals; zero-initialized at load) ------
__device__ float    g_loop[Nn];
__device__ int      g_cnt[Nn];
__device__ int      g_row[Nn+1];
__device__ int      g_woff[Nn];
__device__ int2     g_ced[EAt];      // (src, edge_attr bits)
__device__ float    g_xl[Nn*HID];
__device__ float    g_xr[Nn*HID];
__device__ float    g_h[Nn*HID];
__device__ float    g_pl[Nn*4];
__device__ float    g_pmax[NRED];
__device__ float    g_psum[NRED];

__device__ __forceinline__ float lrelu(float v){ return v > 0.f ? v : 0.2f * v; }

__device__ __forceinline__ float dot8(float4 l0, float4 l1, float4 r0, float4 r1,
                                      float ev, float4 w0, float4 w1,
                                      float4 t0, float4 t1){
    float p = 0.f;
    p += lrelu(l0.x + r0.x + ev*w0.x) * t0.x;
    p += lrelu(l0.y + r0.y + ev*w0.y) * t0.y;
    p += lrelu(l0.z + r0.z + ev*w0.z) * t0.z;
    p += lrelu(l0.w + r0.w + ev*w0.w) * t0.w;
    p += lrelu(l1.x + r1.x + ev*w1.x) * t1.x;
    p += lrelu(l1.y + r1.y + ev*w1.y) * t1.y;
    p += lrelu(l1.z + r1.z + ev*w1.z) * t1.z;
    p += lrelu(l1.w + r1.w + ev*w1.w) * t1.w;
    return p;
}

// ---------------- kernel 1: edge histogram (+loop attr sum)  ||  lin1 ----------------
#define HB 1250   // (Ne+255)/256
__global__ void k_hist_lin1(const int* __restrict__ dst, const float* __restrict__ ea,
                            const float* __restrict__ x,
                            const float* __restrict__ Wl, const float* __restrict__ bl,
                            const float* __restrict__ Wr, const float* __restrict__ br){
    int b = blockIdx.x;
    if(b < HB){
        int e = b*256 + threadIdx.x;
        if(e < Ne){
            int d = dst[e];
            atomicAdd(&g_cnt[d], 1);
            atomicAdd(&g_loop[d], ea[e]);
        }
    } else {
        int t = (b - HB)*256 + threadIdx.x;
        if(t < Nn*64){
            int n = t >> 6, c4 = (t & 63) << 2;
            float4 xv = *(const float4*)(x + n*4);
            float4 l = *(const float4*)(bl + c4);
            float4 r = *(const float4*)(br + c4);
            float4 w;
            w = *(const float4*)(Wl + 0*256 + c4); l.x+=xv.x*w.x; l.y+=xv.x*w.y; l.z+=xv.x*w.z; l.w+=xv.x*w.w;
            w = *(const float4*)(Wl + 1*256 + c4); l.x+=xv.y*w.x; l.y+=xv.y*w.y; l.z+=xv.y*w.z; l.w+=xv.y*w.w;
            w = *(const float4*)(Wl + 2*256 + c4); l.x+=xv.z*w.x; l.y+=xv.z*w.y; l.z+=xv.z*w.z; l.w+=xv.z*w.w;
            w = *(const float4*)(Wl + 3*256 + c4); l.x+=xv.w*w.x; l.y+=xv.w*w.y; l.z+=xv.w*w.z; l.w+=xv.w*w.w;
            w = *(const float4*)(Wr + 0*256 + c4); r.x+=xv.x*w.x; r.y+=xv.x*w.y; r.z+=xv.x*w.z; r.w+=xv.x*w.w;
            w = *(const float4*)(Wr + 1*256 + c4); r.x+=xv.y*w.x; r.y+=xv.y*w.y; r.z+=xv.y*w.z; r.w+=xv.y*w.w;
            w = *(const float4*)(Wr + 2*256 + c4); r.x+=xv.z*w.x; r.y+=xv.z*w.y; r.z+=xv.z*w.z; r.w+=xv.z*w.w;
            w = *(const float4*)(Wr + 3*256 + c4); r.x+=xv.w*w.x; r.y+=xv.w*w.y; r.z+=xv.w*w.z; r.w+=xv.w*w.w;
            *(float4*)(g_xl + n*256 + c4) = l;
            *(float4*)(g_xr + n*256 + c4) = r;
        }
    }
}

// ---------------- kernel 2: scan + prep (single block) ----------------
__global__ void k_scanprep(){
    __shared__ int part[1024];
    const int NP = 10;
    int tid = threadIdx.x;
    int base = tid * NP;
    int cnt[NP], loc[NP];
    int s = 0;
    #pragma unroll
    for(int i = 0; i < NP; i++){
        int idx = base + i;
        int c = (idx < Nn) ? g_cnt[idx] : 0;
        cnt[i] = c;
        loc[i] = s;
        s += (idx < Nn) ? (c + 1) : 0;
    }
    part[tid] = s; __syncthreads();
    for(int o = 1; o < 1024; o <<= 1){
        int v = (tid >= o) ? part[tid - o] : 0;
        __syncthreads();
        if(tid >= o) part[tid] += v;
        __syncthreads();
    }
    int off = (tid > 0) ? part[tid - 1] : 0;
    #pragma unroll
    for(int i = 0; i < NP; i++){
        int idx = base + i;
        if(idx < Nn){
            int rs = off + loc[i];
            int re = rs + cnt[i] + 1;
            g_row[idx] = rs;
            if(idx == Nn-1) g_row[Nn] = re;
            float lp = g_loop[idx] / fmaxf((float)cnt[i], 1.f);
            g_ced[re-1] = make_int2(idx, __float_as_int(lp));
            g_woff[idx] = rs;
        }
    }
}

// ---------------- kernel 3: scatter edges into CSR ----------------
__global__ void k_scatter(const int* __restrict__ src, const int* __restrict__ dst,
                          const float* __restrict__ ea){
    int e = blockIdx.x*blockDim.x + threadIdx.x;
    if(e >= Ne) return;
    int d = dst[e];
    int pos = atomicAdd(&g_woff[d], 1);
    g_ced[pos] = make_int2(src[e], __float_as_int(ea[e]));
}

// ---------------- fused conv (both layers): scalar loop, 1 warp = 1 block = 1 node --
// no-max softmax (logits provably << 88); NSH = shuffle levels (3=conv1, 5=conv2)
template<int NSH>
__global__ void __launch_bounds__(32) k_conv(
        const float* __restrict__ We, const float* __restrict__ att,
        const float* __restrict__ bias, const float* __restrict__ gam,
        const float* __restrict__ bet){
    int n = blockIdx.x;
    int lane = threadIdx.x;
    int c0 = lane * 8;
    const float4* pr = (const float4*)(g_xr + n*HID + c0);
    float4 r0 = pr[0], r1 = pr[1];
    float4 w0 = *(const float4*)(We + c0),  w1 = *(const float4*)(We + c0 + 4);
    float4 t0 = *(const float4*)(att + c0), t1 = *(const float4*)(att + c0 + 4);
    float acc[8] = {0,0,0,0,0,0,0,0};
    float den = 0.f;
    int b = g_row[n], e = g_row[n+1];
    int i = b;
    for(; i + 1 < e; i += 2){
        int2 ed0 = g_ced[i], ed1 = g_ced[i+1];
        float ev0 = __int_as_float(ed0.y), ev1 = __int_as_float(ed1.y);
        const float4* pA = (const float4*)(g_xl + ed0.x*HID + c0);
        const float4* pB = (const float4*)(g_xl + ed1.x*HID + c0);
        float4 a0 = pA[0], a1 = pA[1];
        float4 b0 = pB[0], b1 = pB[1];
        float p0 = dot8(a0, a1, r0, r1, ev0, w0, w1, t0, t1);
        float p1 = dot8(b0, b1, r0, r1, ev1, w0, w1, t0, t1);
        #pragma unroll
        for(int o = 0; o < NSH; o++){
            p0 += __shfl_xor_sync(0xffffffffu, p0, 1 << o);
            p1 += __shfl_xor_sync(0xffffffffu, p1, 1 << o);
        }
        float e0 = __expf(p0);
        float e1 = __expf(p1);
        den += e0 + e1;
        acc[0] += a0.x*e0 + b0.x*e1; acc[1] += a0.y*e0 + b0.y*e1;
        acc[2] += a0.z*e0 + b0.z*e1; acc[3] += a0.w*e0 + b0.w*e1;
        acc[4] += a1.x*e0 + b1.x*e1; acc[5] += a1.y*e0 + b1.y*e1;
        acc[6] += a1.z*e0 + b1.z*e1; acc[7] += a1.w*e0 + b1.w*e1;
    }
    if(i < e){
        int2 ed0 = g_ced[i];
        float ev0 = __int_as_float(ed0.y);
        const float4* pA = (const float4*)(g_xl + ed0.x*HID + c0);
        float4 a0 = pA[0], a1 = pA[1];
        float p0 = dot8(a0, a1, r0, r1, ev0, w0, w1, t0, t1);
        #pragma unroll
        for(int o = 0; o < NSH; o++)
            p0 += __shfl_xor_sync(0xffffffffu, p0, 1 << o);
        float e0 = __expf(p0);
        den += e0;
        acc[0] += a0.x*e0; acc[1] += a0.y*e0;
        acc[2] += a0.z*e0; acc[3] += a0.w*e0;
        acc[4] += a1.x*e0; acc[5] += a1.y*e0;
        acc[6] += a1.z*e0; acc[7] += a1.w*e0;
    }
    float inv = 1.f / den;
    float v[8];
    float s = 0.f;
    #pragma unroll
    for(int k = 0; k < 8; k++){ v[k] = acc[k]*inv + bias[c0+k]; s += v[k]; }
    #pragma unroll
    for(int o = 16; o; o >>= 1) s += __shfl_xor_sync(0xffffffffu, s, o);
    float mu = s * (1.f/256.f);
    float q = 0.f;
    #pragma unroll
    for(int k = 0; k < 8; k++){ float dd = v[k]-mu; q += dd*dd; }
    #pragma unroll
    for(int o = 16; o; o >>= 1) q += __shfl_xor_sync(0xffffffffu, q, o);
    float rstd = rsqrtf(q*(1.f/256.f) + 1e-5f);
    float o0[8];
    #pragma unroll
    for(int k = 0; k < 8; k++)
        o0[k] = fmaxf((v[k]-mu)*rstd*gam[c0+k] + bet[c0+k], 0.f);
    *(float4*)(g_h + n*HID + c0)     = make_float4(o0[0],o0[1],o0[2],o0[3]);
    *(float4*)(g_h + n*HID + c0 + 4) = make_float4(o0[4],o0[5],o0[6],o0[7]);
}

// ---------------- dual GEMM (proven 64x64 fp32 tile), one launch ----------------
__global__ void k_gemm_dual(const float* __restrict__ Wl, const float* __restrict__ bl,
                            const float* __restrict__ Wr, const float* __restrict__ br){
    __shared__ __align__(16) float As[16][68];
    __shared__ __align__(16) float Bs[16][68];
    int half = blockIdx.x >> 2;
    int nblk = blockIdx.x & 3;
    const float* B    = half ? Wr   : Wl;
    const float* bias = half ? br   : bl;
    float*       C    = half ? g_xr : g_xl;
    int m0 = blockIdx.y*64, n0 = nblk*64;
    int t = threadIdx.x;
    int tx = t & 15, ty = t >> 4;
    float acc[4][4] = {};
    int arow = t >> 2, ak = (t & 3) * 4;
    int brow = t >> 4, bc = (t & 15) * 4;
    for(int k0 = 0; k0 < 256; k0 += 16){
        float4 av = make_float4(0.f,0.f,0.f,0.f);
        int gm = m0 + arow;
        if(gm < Nn) av = *(const float4*)(g_h + gm*256 + k0 + ak);
        As[ak+0][arow] = av.x; As[ak+1][arow] = av.y;
        As[ak+2][arow] = av.z; As[ak+3][arow] = av.w;
        *(float4*)&Bs[brow][bc] = *(const float4*)(B + (k0+brow)*256 + n0 + bc);
        __syncthreads();
        #pragma unroll
        for(int kk = 0; kk < 16; kk++){
            float4 a = *(float4*)&As[kk][ty*4];
            float4 b = *(float4*)&Bs[kk][tx*4];
            acc[0][0]+=a.x*b.x; acc[0][1]+=a.x*b.y; acc[0][2]+=a.x*b.z; acc[0][3]+=a.x*b.w;
            acc[1][0]+=a.y*b.x; acc[1][1]+=a.y*b.y; acc[1][2]+=a.y*b.z; acc[1][3]+=a.y*b.w;
            acc[2][0]+=a.z*b.x; acc[2][1]+=a.z*b.y; acc[2][2]+=a.z*b.z; acc[2][3]+=a.z*b.w;
            acc[3][0]+=a.w*b.x; acc[3][1]+=a.w*b.y; acc[3][2]+=a.w*b.z; acc[3][3]+=a.w*b.w;
        }
        __syncthreads();
    }
    #pragma unroll
    for(int i = 0; i < 4; i++){
        int gm = m0 + ty*4 + i;
        if(gm >= Nn) continue;
        #pragma unroll
        for(int j = 0; j < 4; j++){
            int col = n0 + tx*4 + j;
            C[gm*256 + col] = acc[i][j] + bias[col];
        }
    }
}

// ---------------- policy GEMM (fp32 mainloop) + fused final projection ----------
__global__ void k_gemm_pol(const float* __restrict__ Wp1, const float* __restrict__ bp1,
                           const float* __restrict__ Wp2, const float* __restrict__ bp2){
    __shared__ __align__(16) float As[16][68];
    __shared__ __align__(16) float Bs[16][132];
    int m0 = blockIdx.x * 64;
    int t = threadIdx.x;
    int tx = t & 15, ty = t >> 4;
    int ar = t >> 2, ak = (t & 3) * 4;
    int br_ = t >> 4, bc = (t & 15) * 8;
    float acc[4][8] = {};
    for(int k0 = 0; k0 < 256; k0 += 16){
        float4 av = make_float4(0.f,0.f,0.f,0.f);
        int gm = m0 + ar;
        if(gm < Nn) av = *(const float4*)(g_h + gm*256 + k0 + ak);
        As[ak+0][ar] = av.x; As[ak+1][ar] = av.y;
        As[ak+2][ar] = av.z; As[ak+3][ar] = av.w;
        *(float4*)&Bs[br_][bc]   = *(const float4*)(Wp1 + (k0+br_)*128 + bc);
        *(float4*)&Bs[br_][bc+4] = *(const float4*)(Wp1 + (k0+br_)*128 + bc + 4);
        __syncthreads();
        #pragma unroll
        for(int kk = 0; kk < 16; kk++){
            float4 a = *(float4*)&As[kk][ty*4];
            float4 b0 = *(float4*)&Bs[kk][tx*8];
            float4 b1 = *(float4*)&Bs[kk][tx*8+4];
            float av4[4] = {a.x,a.y,a.z,a.w};
            float bv[8] = {b0.x,b0.y,b0.z,b0.w,b1.x,b1.y,b1.z,b1.w};
            #pragma unroll
            for(int i = 0; i < 4; i++)
                #pragma unroll
                for(int j = 0; j < 8; j++)
                    acc[i][j] += av4[i]*bv[j];
        }
        __syncthreads();
    }
    float4 bpA = *(const float4*)(bp1 + tx*8);
    float4 bpB = *(const float4*)(bp1 + tx*8 + 4);
    float bb[8] = {bpA.x,bpA.y,bpA.z,bpA.w,bpB.x,bpB.y,bpB.z,bpB.w};
    float4 wv[8];
    const float4* wp = (const float4*)(Wp2 + tx*32);
    #pragma unroll
    for(int j = 0; j < 8; j++) wv[j] = wp[j];
    float part[4][4];
    #pragma unroll
    for(int i = 0; i < 4; i++){
        part[i][0] = part[i][1] = part[i][2] = part[i][3] = 0.f;
        bool ok = (m0 + ty*4 + i) < Nn;
        #pragma unroll
        for(int j = 0; j < 8; j++){
            float v0 = ok ? fmaxf(acc[i][j] + bb[j], 0.f) : 0.f;
            part[i][0] += v0*wv[j].x;
            part[i][1] += v0*wv[j].y;
            part[i][2] += v0*wv[j].z;
            part[i][3] += v0*wv[j].w;
        }
    }
    #pragma unroll
    for(int i = 0; i < 4; i++)
        #pragma unroll
        for(int c = 0; c < 4; c++){
            #pragma unroll
            for(int o = 1; o < 16; o <<= 1)
                part[i][c] += __shfl_xor_sync(0xffffffffu, part[i][c], o);
        }
    if(tx == 0){
        #pragma unroll
        for(int i = 0; i < 4; i++){
            int gm = m0 + ty*4 + i;
            if(gm < Nn){
                float4 r4 = make_float4(part[i][0]+bp2[0], part[i][1]+bp2[1],
                                        part[i][2]+bp2[2], part[i][3]+bp2[3]);
                *(float4*)(g_pl + gm*4) = r4;
            }
        }
    }
}

// ---------------- two-phase global softmax over 40000 logits ----------------
__global__ void k_red1(){
    __shared__ float sm[256];
    int bid = blockIdx.x, tid = threadIdx.x;
    const int chunk = (Nn*4 + NRED - 1) / NRED;
    int lo = bid*chunk, hi = min(lo + chunk, Nn*4);
    float m = -3.4e38f;
    for(int i = lo + tid; i < hi; i += 256) m = fmaxf(m, g_pl[i]);
    sm[tid] = m; __syncthreads();
    for(int o = 128; o > 0; o >>= 1){ if(tid < o) sm[tid] = fmaxf(sm[tid], sm[tid+o]); __syncthreads(); }
    float mx = sm[0]; __syncthreads();
    float s = 0.f;
    for(int i = lo + tid; i < hi; i += 256) s += __expf(g_pl[i] - mx);
    sm[tid] = s; __syncthreads();
    for(int o = 128; o > 0; o >>= 1){ if(tid < o) sm[tid] += sm[tid+o]; __syncthreads(); }
    if(tid == 0){ g_pmax[bid] = mx; g_psum[bid] = sm[0]; }
}
// output (combines the NRED partials in-block) + restore state for next replay
__global__ void k_out(float* __restrict__ out){
    __shared__ float sMS[2];
    if(threadIdx.x == 0){
        float M = -3.4e38f;
        #pragma unroll
        for(int j = 0; j < NRED; j++) M = fmaxf(M, g_pmax[j]);
        float S = 0.f;
        #pragma unroll
        for(int j = 0; j < NRED; j++) S += g_psum[j] * __expf(g_pmax[j] - M);
        sMS[0] = M; sMS[1] = 1.f / S;
    }
    __syncthreads();
    int i = blockIdx.x*blockDim.x + threadIdx.x;
    if(i < Nn*4) out[i] = __expf(g_pl[i] - sMS[0]) * sMS[1];
    if(i < Nn){ g_cnt[i] = 0; g_loop[i] = 0.f; }
}

// ---------------- launch ----------------
extern "C" void kernel_launch(void* const* d_in, const int* in_sizes, int n_in,
                              void* d_out, int out_size){
    const float* x     = (const float*)d_in[0];
    const int*   ei    = (const int*)  d_in[1];
    const float* ea    = (const float*)d_in[2];
    const float* Wl1   = (const float*)d_in[3];
    const float* bl1   = (const float*)d_in[4];
    const float* Wr1   = (const float*)d_in[5];
    const float* br1   = (const float*)d_in[6];
    const float* We1   = (const float*)d_in[7];
    const float* att1  = (const float*)d_in[8];
    const float* bias1 = (const float*)d_in[9];
    const float* g1    = (const float*)d_in[10];
    const float* be1   = (const float*)d_in[11];
    const float* Wl2   = (const float*)d_in[12];
    const float* bl2   = (const float*)d_in[13];
    const float* Wr2   = (const float*)d_in[14];
    const float* br2   = (const float*)d_in[15];
    const float* We2   = (const float*)d_in[16];
    const float* att2  = (const float*)d_in[17];
    const float* bias2 = (const float*)d_in[18];
    const float* g2    = (const float*)d_in[19];
    const float* be2   = (const float*)d_in[20];
    const float* Wp1   = (const float*)d_in[21];
    const float* bp1   = (const float*)d_in[22];
    const float* Wp2   = (const float*)d_in[23];
    const float* bp2   = (const float*)d_in[24];
    const int* src = ei;
    const int* dst = ei + Ne;
    float* out = (float*)d_out;

    const int TB = 256;

    // CSR build + conv1 linear (merged)
    k_hist_lin1<<<HB + (Nn*64+TB-1)/TB, TB>>>(dst, ea, x, Wl1, bl1, Wr1, br1);
    k_scanprep<<<1, 1024>>>();
    k_scatter<<<(Ne+TB-1)/TB, TB>>>(src, dst, ea);

    // conv1 (heads=4: 3 shuffle levels) — one warp-block per node
    k_conv<3><<<Nn, 32>>>(We1, att1, bias1, g1, be1);

    // conv2
    k_gemm_dual<<<dim3(8, (Nn+63)/64), 256>>>(Wl2, bl2, Wr2, br2);
    k_conv<5><<<Nn, 32>>>(We2, att2, bias2, g2, be2);

    // policy head (fused final projection)
    k_gemm_pol<<<(Nn+63)/64, 256>>>(Wp1, bp1, Wp2, bp2);

    // global softmax (two-phase)
    k_red1<<<NRED, 256>>>();
    k_out<<<(Nn*4+TB-1)/TB, TB>>>(out);
}

// round 8
// speedup vs baseline: 1.1015x; 1.0223x over previous
#include <cuda_runtime.h>

#define Nn   10000
#define Ne   320000
#define EAt  330000      // edges + self loops
#define HID  256
#define NRED 20          // partial-reduction blocks for final softmax

// ---------------- scratch (static device globals; zero-initialized at load) ------
__device__ float    g_loop[Nn];
__device__ int      g_cnt[Nn];
__device__ int      g_row[Nn+1];
__device__ int      g_woff[Nn];
__device__ int2     g_ced[EAt];      // (src, edge_attr bits)
__device__ float    g_xl[Nn*HID];
__device__ float    g_xr[Nn*HID];
__device__ float    g_h[Nn*HID];
__device__ float    g_pl[Nn*4];
__device__ float    g_pmax[NRED];
__device__ float    g_psum[NRED];

__device__ __forceinline__ float lrelu(float v){ return v > 0.f ? v : 0.2f * v; }

__device__ __forceinline__ float dot8(float4 l0, float4 l1, float4 r0, float4 r1,
                                      float ev, float4 w0, float4 w1,
                                      float4 t0, float4 t1){
    float p = 0.f;
    p += lrelu(l0.x + r0.x + ev*w0.x) * t0.x;
    p += lrelu(l0.y + r0.y + ev*w0.y) * t0.y;
    p += lrelu(l0.z + r0.z + ev*w0.z) * t0.z;
    p += lrelu(l0.w + r0.w + ev*w0.w) * t0.w;
    p += lrelu(l1.x + r1.x + ev*w1.x) * t1.x;
    p += lrelu(l1.y + r1.y + ev*w1.y) * t1.y;
    p += lrelu(l1.z + r1.z + ev*w1.z) * t1.z;
    p += lrelu(l1.w + r1.w + ev*w1.w) * t1.w;
    return p;
}

// ---------------- kernel 1: edge histogram (+loop attr sum)  ||  lin1 ----------------
#define HB 1250   // (Ne+255)/256
__global__ void k_hist_lin1(const int* __restrict__ dst, const float* __restrict__ ea,
                            const float* __restrict__ x,
                            const float* __restrict__ Wl, const float* __restrict__ bl,
                            const float* __restrict__ Wr, const float* __restrict__ br){
    int b = blockIdx.x;
    if(b < HB){
        int e = b*256 + threadIdx.x;
        if(e < Ne){
            int d = dst[e];
            atomicAdd(&g_cnt[d], 1);
            atomicAdd(&g_loop[d], ea[e]);
        }
    } else {
        int t = (b - HB)*256 + threadIdx.x;
        if(t < Nn*64){
            int n = t >> 6, c4 = (t & 63) << 2;
            float4 xv = *(const float4*)(x + n*4);
            float4 l = *(const float4*)(bl + c4);
            float4 r = *(const float4*)(br + c4);
            float4 w;
            w = *(const float4*)(Wl + 0*256 + c4); l.x+=xv.x*w.x; l.y+=xv.x*w.y; l.z+=xv.x*w.z; l.w+=xv.x*w.w;
            w = *(const float4*)(Wl + 1*256 + c4); l.x+=xv.y*w.x; l.y+=xv.y*w.y; l.z+=xv.y*w.z; l.w+=xv.y*w.w;
            w = *(const float4*)(Wl + 2*256 + c4); l.x+=xv.z*w.x; l.y+=xv.z*w.y; l.z+=xv.z*w.z; l.w+=xv.z*w.w;
            w = *(const float4*)(Wl + 3*256 + c4); l.x+=xv.w*w.x; l.y+=xv.w*w.y; l.z+=xv.w*w.z; l.w+=xv.w*w.w;
            w = *(const float4*)(Wr + 0*256 + c4); r.x+=xv.x*w.x; r.y+=xv.x*w.y; r.z+=xv.x*w.z; r.w+=xv.x*w.w;
            w = *(const float4*)(Wr + 1*256 + c4); r.x+=xv.y*w.x; r.y+=xv.y*w.y; r.z+=xv.y*w.z; r.w+=xv.y*w.w;
            w = *(const float4*)(Wr + 2*256 + c4); r.x+=xv.z*w.x; r.y+=xv.z*w.y; r.z+=xv.z*w.z; r.w+=xv.z*w.w;
            w = *(const float4*)(Wr + 3*256 + c4); r.x+=xv.w*w.x; r.y+=xv.w*w.y; r.z+=xv.w*w.z; r.w+=xv.w*w.w;
            *(float4*)(g_xl + n*256 + c4) = l;
            *(float4*)(g_xr + n*256 + c4) = r;
        }
    }
}

// ---------------- kernel 2: scan + prep (single block) ----------------
__global__ void k_scanprep(){
    __shared__ int part[1024];
    const int NP = 10;
    int tid = threadIdx.x;
    int base = tid * NP;
    int cnt[NP], loc[NP];
    int s = 0;
    #pragma unroll
    for(int i = 0; i < NP; i++){
        int idx = base + i;
        int c = (idx < Nn) ? g_cnt[idx] : 0;
        cnt[i] = c;
        loc[i] = s;
        s += (idx < Nn) ? (c + 1) : 0;
    }
    part[tid] = s; __syncthreads();
    for(int o = 1; o < 1024; o <<= 1){
        int v = (tid >= o) ? part[tid - o] : 0;
        __syncthreads();
        if(tid >= o) part[tid] += v;
        __syncthreads();
    }
    int off = (tid > 0) ? part[tid - 1] : 0;
    #pragma unroll
    for(int i = 0; i < NP; i++){
        int idx = base + i;
        if(idx < Nn){
            int rs = off + loc[i];
            int re = rs + cnt[i] + 1;
            g_row[idx] = rs;
            if(idx == Nn-1) g_row[Nn] = re;
            float lp = g_loop[idx] / fmaxf((float)cnt[i], 1.f);
            g_ced[re-1] = make_int2(idx, __float_as_int(lp));
            g_woff[idx] = rs;
        }
    }
}

// ---------------- kernel 3: scatter edges into CSR ----------------
__global__ void k_scatter(const int* __restrict__ src, const int* __restrict__ dst,
                          const float* __restrict__ ea){
    int e = blockIdx.x*blockDim.x + threadIdx.x;
    if(e >= Ne) return;
    int d = dst[e];
    int pos = atomicAdd(&g_woff[d], 1);
    g_ced[pos] = make_int2(src[e], __float_as_int(ea[e]));
}

// ---------------- fused conv1 (low-rank aggregation over 4-dim input x) ----------
// out_h = (Σ_e α_eh · x[s_e]) @ Wl1_h + bl1_h   (exact: Σα=1 per head, xl rank-4)
__global__ void __launch_bounds__(32) k_conv1lr(
        const float* __restrict__ x,
        const float* __restrict__ Wl, const float* __restrict__ bl,
        const float* __restrict__ We, const float* __restrict__ att,
        const float* __restrict__ bias, const float* __restrict__ gam,
        const float* __restrict__ bet){
    int n = blockIdx.x;
    int lane = threadIdx.x;
    int c0 = lane * 8;
    const float4* pr = (const float4*)(g_xr + n*HID + c0);
    float4 r0 = pr[0], r1 = pr[1];
    float4 w0 = *(const float4*)(We + c0),  w1 = *(const float4*)(We + c0 + 4);
    float4 t0 = *(const float4*)(att + c0), t1 = *(const float4*)(att + c0 + 4);
    int j = lane & 3;           // input-feature index this lane accumulates
    float acc1 = 0.f, den = 0.f;
    int b = g_row[n], e = g_row[n+1];
    int i = b;
    for(; i + 1 < e; i += 2){
        int2 ed0 = g_ced[i], ed1 = g_ced[i+1];
        float ev0 = __int_as_float(ed0.y), ev1 = __int_as_float(ed1.y);
        const float4* pA = (const float4*)(g_xl + ed0.x*HID + c0);
        const float4* pB = (const float4*)(g_xl + ed1.x*HID + c0);
        float4 a0 = pA[0], a1 = pA[1];
        float4 b0 = pB[0], b1 = pB[1];
        float xs0 = x[ed0.x*4 + j];
        float xs1 = x[ed1.x*4 + j];
        float p0 = dot8(a0, a1, r0, r1, ev0, w0, w1, t0, t1);
        float p1 = dot8(b0, b1, r0, r1, ev1, w0, w1, t0, t1);
        #pragma unroll
        for(int o = 0; o < 3; o++){
            p0 += __shfl_xor_sync(0xffffffffu, p0, 1 << o);
            p1 += __shfl_xor_sync(0xffffffffu, p1, 1 << o);
        }
        float e0 = __expf(p0);
        float e1 = __expf(p1);
        den += e0 + e1;
        acc1 += xs0*e0 + xs1*e1;
    }
    if(i < e){
        int2 ed0 = g_ced[i];
        float ev0 = __int_as_float(ed0.y);
        const float4* pA = (const float4*)(g_xl + ed0.x*HID + c0);
        float4 a0 = pA[0], a1 = pA[1];
        float xs0 = x[ed0.x*4 + j];
        float p0 = dot8(a0, a1, r0, r1, ev0, w0, w1, t0, t1);
        #pragma unroll
        for(int o = 0; o < 3; o++)
            p0 += __shfl_xor_sync(0xffffffffu, p0, 1 << o);
        float e0 = __expf(p0);
        den += e0;
        acc1 += xs0*e0;
    }
    // epilogue: reconstruct 8 channels from 4-dim aggregate, + bl1 + bias, LN, ReLU
    float inv = 1.f / den;                 // per-head (identical within 8-lane group)
    int h8 = lane & 24;                    // head base lane
    float ax0 = __shfl_sync(0xffffffffu, acc1, h8+0) * inv;
    float ax1 = __shfl_sync(0xffffffffu, acc1, h8+1) * inv;
    float ax2 = __shfl_sync(0xffffffffu, acc1, h8+2) * inv;
    float ax3 = __shfl_sync(0xffffffffu, acc1, h8+3) * inv;
    float4 wr0A = *(const float4*)(Wl + 0*256 + c0), wr0B = *(const float4*)(Wl + 0*256 + c0 + 4);
    float4 wr1A = *(const float4*)(Wl + 1*256 + c0), wr1B = *(const float4*)(Wl + 1*256 + c0 + 4);
    float4 wr2A = *(const float4*)(Wl + 2*256 + c0), wr2B = *(const float4*)(Wl + 2*256 + c0 + 4);
    float4 wr3A = *(const float4*)(Wl + 3*256 + c0), wr3B = *(const float4*)(Wl + 3*256 + c0 + 4);
    float4 blA = *(const float4*)(bl + c0),   blB = *(const float4*)(bl + c0 + 4);
    float4 biA = *(const float4*)(bias + c0), biB = *(const float4*)(bias + c0 + 4);
    float v[8];
    v[0] = ax0*wr0A.x + ax1*wr1A.x + ax2*wr2A.x + ax3*wr3A.x + blA.x + biA.x;
    v[1] = ax0*wr0A.y + ax1*wr1A.y + ax2*wr2A.y + ax3*wr3A.y + blA.y + biA.y;
    v[2] = ax0*wr0A.z + ax1*wr1A.z + ax2*wr2A.z + ax3*wr3A.z + blA.z + biA.z;
    v[3] = ax0*wr0A.w + ax1*wr1A.w + ax2*wr2A.w + ax3*wr3A.w + blA.w + biA.w;
    v[4] = ax0*wr0B.x + ax1*wr1B.x + ax2*wr2B.x + ax3*wr3B.x + blB.x + biB.x;
    v[5] = ax0*wr0B.y + ax1*wr1B.y + ax2*wr2B.y + ax3*wr3B.y + blB.y + biB.y;
    v[6] = ax0*wr0B.z + ax1*wr1B.z + ax2*wr2B.z + ax3*wr3B.z + blB.z + biB.z;
    v[7] = ax0*wr0B.w + ax1*wr1B.w + ax2*wr2B.w + ax3*wr3B.w + blB.w + biB.w;
    float s = 0.f;
    #pragma unroll
    for(int k = 0; k < 8; k++) s += v[k];
    #pragma unroll
    for(int o = 16; o; o >>= 1) s += __shfl_xor_sync(0xffffffffu, s, o);
    float mu = s * (1.f/256.f);
    float q = 0.f;
    #pragma unroll
    for(int k = 0; k < 8; k++){ float dd = v[k]-mu; q += dd*dd; }
    #pragma unroll
    for(int o = 16; o; o >>= 1) q += __shfl_xor_sync(0xffffffffu, q, o);
    float rstd = rsqrtf(q*(1.f/256.f) + 1e-5f);
    float4 gA = *(const float4*)(gam + c0), gB = *(const float4*)(gam + c0 + 4);
    float4 eA = *(const float4*)(bet + c0), eB = *(const float4*)(bet + c0 + 4);
    float gv[8] = {gA.x,gA.y,gA.z,gA.w,gB.x,gB.y,gB.z,gB.w};
    float ev[8] = {eA.x,eA.y,eA.z,eA.w,eB.x,eB.y,eB.z,eB.w};
    float o0[8];
    #pragma unroll
    for(int k = 0; k < 8; k++)
        o0[k] = fmaxf((v[k]-mu)*rstd*gv[k] + ev[k], 0.f);
    *(float4*)(g_h + n*HID + c0)     = make_float4(o0[0],o0[1],o0[2],o0[3]);
    *(float4*)(g_h + n*HID + c0 + 4) = make_float4(o0[4],o0[5],o0[6],o0[7]);
}

// ---------------- fused conv2 (H=1, C=256): scalar loop, warp-block per node -----
__global__ void __launch_bounds__(32) k_conv2(
        const float* __restrict__ We, const float* __restrict__ att,
        const float* __restrict__ bias, const float* __restrict__ gam,
        const float* __restrict__ bet){
    int n = blockIdx.x;
    int lane = threadIdx.x;
    int c0 = lane * 8;
    const float4* pr = (const float4*)(g_xr + n*HID + c0);
    float4 r0 = pr[0], r1 = pr[1];
    float4 w0 = *(const float4*)(We + c0),  w1 = *(const float4*)(We + c0 + 4);
    float4 t0 = *(const float4*)(att + c0), t1 = *(const float4*)(att + c0 + 4);
    float acc[8] = {0,0,0,0,0,0,0,0};
    float den = 0.f;
    int b = g_row[n], e = g_row[n+1];
    int i = b;
    for(; i + 1 < e; i += 2){
        int2 ed0 = g_ced[i], ed1 = g_ced[i+1];
        float ev0 = __int_as_float(ed0.y), ev1 = __int_as_float(ed1.y);
        const float4* pA = (const float4*)(g_xl + ed0.x*HID + c0);
        const float4* pB = (const float4*)(g_xl + ed1.x*HID + c0);
        float4 a0 = pA[0], a1 = pA[1];
        float4 b0 = pB[0], b1 = pB[1];
        float p0 = dot8(a0, a1, r0, r1, ev0, w0, w1, t0, t1);
        float p1 = dot8(b0, b1, r0, r1, ev1, w0, w1, t0, t1);
        #pragma unroll
        for(int o = 0; o < 5; o++){
            p0 += __shfl_xor_sync(0xffffffffu, p0, 1 << o);
            p1 += __shfl_xor_sync(0xffffffffu, p1, 1 << o);
        }
        float e0 = __expf(p0);
        float e1 = __expf(p1);
        den += e0 + e1;
        acc[0] += a0.x*e0 + b0.x*e1; acc[1] += a0.y*e0 + b0.y*e1;
        acc[2] += a0.z*e0 + b0.z*e1; acc[3] += a0.w*e0 + b0.w*e1;
        acc[4] += a1.x*e0 + b1.x*e1; acc[5] += a1.y*e0 + b1.y*e1;
        acc[6] += a1.z*e0 + b1.z*e1; acc[7] += a1.w*e0 + b1.w*e1;
    }
    if(i < e){
        int2 ed0 = g_ced[i];
        float ev0 = __int_as_float(ed0.y);
        const float4* pA = (const float4*)(g_xl + ed0.x*HID + c0);
        float4 a0 = pA[0], a1 = pA[1];
        float p0 = dot8(a0, a1, r0, r1, ev0, w0, w1, t0, t1);
        #pragma unroll
        for(int o = 0; o < 5; o++)
            p0 += __shfl_xor_sync(0xffffffffu, p0, 1 << o);
        float e0 = __expf(p0);
        den += e0;
        acc[0] += a0.x*e0; acc[1] += a0.y*e0;
        acc[2] += a0.z*e0; acc[3] += a0.w*e0;
        acc[4] += a1.x*e0; acc[5] += a1.y*e0;
        acc[6] += a1.z*e0; acc[7] += a1.w*e0;
    }
    float inv = 1.f / den;
    float4 biA = *(const float4*)(bias + c0), biB = *(const float4*)(bias + c0 + 4);
    float bi[8] = {biA.x,biA.y,biA.z,biA.w,biB.x,biB.y,biB.z,biB.w};
    float v[8];
    float s = 0.f;
    #pragma unroll
    for(int k = 0; k < 8; k++){ v[k] = acc[k]*inv + bi[k]; s += v[k]; }
    #pragma unroll
    for(int o = 16; o; o >>= 1) s += __shfl_xor_sync(0xffffffffu, s, o);
    float mu = s * (1.f/256.f);
    float q = 0.f;
    #pragma unroll
    for(int k = 0; k < 8; k++){ float dd = v[k]-mu; q += dd*dd; }
    #pragma unroll
    for(int o = 16; o; o >>= 1) q += __shfl_xor_sync(0xffffffffu, q, o);
    float rstd = rsqrtf(q*(1.f/256.f) + 1e-5f);
    float4 gA = *(const float4*)(gam + c0), gB = *(const float4*)(gam + c0 + 4);
    float4 eA = *(const float4*)(bet + c0), eB = *(const float4*)(bet + c0 + 4);
    float gv[8] = {gA.x,gA.y,gA.z,gA.w,gB.x,gB.y,gB.z,gB.w};
    float evv[8] = {eA.x,eA.y,eA.z,eA.w,eB.x,eB.y,eB.z,eB.w};
    float o0[8];
    #pragma unroll
    for(int k = 0; k < 8; k++)
        o0[k] = fmaxf((v[k]-mu)*rstd*gv[k] + evv[k], 0.f);
    *(float4*)(g_h + n*HID + c0)     = make_float4(o0[0],o0[1],o0[2],o0[3]);
    *(float4*)(g_h + n*HID + c0 + 4) = make_float4(o0[4],o0[5],o0[6],o0[7]);
}

// ---------------- dual GEMM (proven 64x64 fp32 tile), one launch ----------------
__global__ void k_gemm_dual(const float* __restrict__ Wl, const float* __restrict__ bl,
                            const float* __restrict__ Wr, const float* __restrict__ br){
    __shared__ __align__(16) float As[16][68];
    __shared__ __align__(16) float Bs[16][68];
    int half = blockIdx.x >> 2;
    int nblk = blockIdx.x & 3;
    const float* B    = half ? Wr   : Wl;
    const float* bias = half ? br   : bl;
    float*       C    = half ? g_xr : g_xl;
    int m0 = blockIdx.y*64, n0 = nblk*64;
    int t = threadIdx.x;
    int tx = t & 15, ty = t >> 4;
    float acc[4][4] = {};
    int arow = t >> 2, ak = (t & 3) * 4;
    int brow = t >> 4, bc = (t & 15) * 4;
    for(int k0 = 0; k0 < 256; k0 += 16){
        float4 av = make_float4(0.f,0.f,0.f,0.f);
        int gm = m0 + arow;
        if(gm < Nn) av = *(const float4*)(g_h + gm*256 + k0 + ak);
        As[ak+0][arow] = av.x; As[ak+1][arow] = av.y;
        As[ak+2][arow] = av.z; As[ak+3][arow] = av.w;
        *(float4*)&Bs[brow][bc] = *(const float4*)(B + (k0+brow)*256 + n0 + bc);
        __syncthreads();
        #pragma unroll
        for(int kk = 0; kk < 16; kk++){
            float4 a = *(float4*)&As[kk][ty*4];
            float4 b = *(float4*)&Bs[kk][tx*4];
            acc[0][0]+=a.x*b.x; acc[0][1]+=a.x*b.y; acc[0][2]+=a.x*b.z; acc[0][3]+=a.x*b.w;
            acc[1][0]+=a.y*b.x; acc[1][1]+=a.y*b.y; acc[1][2]+=a.y*b.z; acc[1][3]+=a.y*b.w;
            acc[2][0]+=a.z*b.x; acc[2][1]+=a.z*b.y; acc[2][2]+=a.z*b.z; acc[2][3]+=a.z*b.w;
            acc[3][0]+=a.w*b.x; acc[3][1]+=a.w*b.y; acc[3][2]+=a.w*b.z; acc[3][3]+=a.w*b.w;
        }
        __syncthreads();
    }
    #pragma unroll
    for(int i = 0; i < 4; i++){
        int gm = m0 + ty*4 + i;
        if(gm >= Nn) continue;
        #pragma unroll
        for(int j = 0; j < 4; j++){
            int col = n0 + tx*4 + j;
            C[gm*256 + col] = acc[i][j] + bias[col];
        }
    }
}

// ---------------- policy GEMM (fp32 mainloop) + fused final projection ----------
__global__ void k_gemm_pol(const float* __restrict__ Wp1, const float* __restrict__ bp1,
                           const float* __restrict__ Wp2, const float* __restrict__ bp2){
    __shared__ __align__(16) float As[16][68];
    __shared__ __align__(16) float Bs[16][132];
    int m0 = blockIdx.x * 64;
    int t = threadIdx.x;
    int tx = t & 15, ty = t >> 4;
    int ar = t >> 2, ak = (t & 3) * 4;
    int br_ = t >> 4, bc = (t & 15) * 8;
    float acc[4][8] = {};
    for(int k0 = 0; k0 < 256; k0 += 16){
        float4 av = make_float4(0.f,0.f,0.f,0.f);
        int gm = m0 + ar;
        if(gm < Nn) av = *(const float4*)(g_h + gm*256 + k0 + ak);
        As[ak+0][ar] = av.x; As[ak+1][ar] = av.y;
        As[ak+2][ar] = av.z; As[ak+3][ar] = av.w;
        *(float4*)&Bs[br_][bc]   = *(const float4*)(Wp1 + (k0+br_)*128 + bc);
        *(float4*)&Bs[br_][bc+4] = *(const float4*)(Wp1 + (k0+br_)*128 + bc + 4);
        __syncthreads();
        #pragma unroll
        for(int kk = 0; kk < 16; kk++){
            float4 a = *(float4*)&As[kk][ty*4];
            float4 b0 = *(float4*)&Bs[kk][tx*8];
            float4 b1 = *(float4*)&Bs[kk][tx*8+4];
            float av4[4] = {a.x,a.y,a.z,a.w};
            float bv[8] = {b0.x,b0.y,b0.z,b0.w,b1.x,b1.y,b1.z,b1.w};
            #pragma unroll
            for(int i = 0; i < 4; i++)
                #pragma unroll
                for(int j = 0; j < 8; j++)
                    acc[i][j] += av4[i]*bv[j];
        }
        __syncthreads();
    }
    float4 bpA = *(const float4*)(bp1 + tx*8);
    float4 bpB = *(const float4*)(bp1 + tx*8 + 4);
    float bb[8] = {bpA.x,bpA.y,bpA.z,bpA.w,bpB.x,bpB.y,bpB.z,bpB.w};
    float4 wv[8];
    const float4* wp = (const float4*)(Wp2 + tx*32);
    #pragma unroll
    for(int j = 0; j < 8; j++) wv[j] = wp[j];
    float part[4][4];
    #pragma unroll
    for(int i = 0; i < 4; i++){
        part[i][0] = part[i][1] = part[i][2] = part[i][3] = 0.f;
        bool ok = (m0 + ty*4 + i) < Nn;
        #pragma unroll
        for(int j = 0; j < 8; j++){
            float v0 = ok ? fmaxf(acc[i][j] + bb[j], 0.f) : 0.f;
            part[i][0] += v0*wv[j].x;
            part[i][1] += v0*wv[j].y;
            part[i][2] += v0*wv[j].z;
            part[i][3] += v0*wv[j].w;
        }
    }
    #pragma unroll
    for(int i = 0; i < 4; i++)
        #pragma unroll
        for(int c = 0; c < 4; c++){
            #pragma unroll
            for(int o = 1; o < 16; o <<= 1)
                part[i][c] += __shfl_xor_sync(0xffffffffu, part[i][c], o);
        }
    if(tx == 0){
        #pragma unroll
        for(int i = 0; i < 4; i++){
            int gm = m0 + ty*4 + i;
            if(gm < Nn){
                float4 r4 = make_float4(part[i][0]+bp2[0], part[i][1]+bp2[1],
                                        part[i][2]+bp2[2], part[i][3]+bp2[3]);
                *(float4*)(g_pl + gm*4) = r4;
            }
        }
    }
}

// ---------------- two-phase global softmax over 40000 logits ----------------
__global__ void k_red1(){
    __shared__ float sm[256];
    int bid = blockIdx.x, tid = threadIdx.x;
    const int chunk = (Nn*4 + NRED - 1) / NRED;
    int lo = bid*chunk, hi = min(lo + chunk, Nn*4);
    float m = -3.4e38f;
    for(int i = lo + tid; i < hi; i += 256) m = fmaxf(m, g_pl[i]);
    sm[tid] = m; __syncthreads();
    for(int o = 128; o > 0; o >>= 1){ if(tid < o) sm[tid] = fmaxf(sm[tid], sm[tid+o]); __syncthreads(); }
    float mx = sm[0]; __syncthreads();
    float s = 0.f;
    for(int i = lo + tid; i < hi; i += 256) s += __expf(g_pl[i] - mx);
    sm[tid] = s; __syncthreads();
    for(int o = 128; o > 0; o >>= 1){ if(tid < o) sm[tid] += sm[tid+o]; __syncthreads(); }
    if(tid == 0){ g_pmax[bid] = mx; g_psum[bid] = sm[0]; }
}
// output (combines the NRED partials in-block) + restore state for next replay
__global__ void k_out(float* __restrict__ out){
    __shared__ float sMS[2];
    if(threadIdx.x == 0){
        float M = -3.4e38f;
        #pragma unroll
        for(int j = 0; j < NRED; j++) M = fmaxf(M, g_pmax[j]);
        float S = 0.f;
        #pragma unroll
        for(int j = 0; j < NRED; j++) S += g_psum[j] * __expf(g_pmax[j] - M);
        sMS[0] = M; sMS[1] = 1.f / S;
    }
    __syncthreads();
    int i = blockIdx.x*blockDim.x + threadIdx.x;
    if(i < Nn*4) out[i] = __expf(g_pl[i] - sMS[0]) * sMS[1];
    if(i < Nn){ g_cnt[i] = 0; g_loop[i] = 0.f; }
}

// ---------------- launch ----------------
extern "C" void kernel_launch(void* const* d_in, const int* in_sizes, int n_in,
                              void* d_out, int out_size){
    const float* x     = (const float*)d_in[0];
    const int*   ei    = (const int*)  d_in[1];
    const float* ea    = (const float*)d_in[2];
    const float* Wl1   = (const float*)d_in[3];
    const float* bl1   = (const float*)d_in[4];
    const float* Wr1   = (const float*)d_in[5];
    const float* br1   = (const float*)d_in[6];
    const float* We1   = (const float*)d_in[7];
    const float* att1  = (const float*)d_in[8];
    const float* bias1 = (const float*)d_in[9];
    const float* g1    = (const float*)d_in[10];
    const float* be1   = (const float*)d_in[11];
    const float* Wl2   = (const float*)d_in[12];
    const float* bl2   = (const float*)d_in[13];
    const float* Wr2   = (const float*)d_in[14];
    const float* br2   = (const float*)d_in[15];
    const float* We2   = (const float*)d_in[16];
    const float* att2  = (const float*)d_in[17];
    const float* bias2 = (const float*)d_in[18];
    const float* g2    = (const float*)d_in[19];
    const float* be2   = (const float*)d_in[20];
    const float* Wp1   = (const float*)d_in[21];
    const float* bp1   = (const float*)d_in[22];
    const float* Wp2   = (const float*)d_in[23];
    const float* bp2   = (const float*)d_in[24];
    const int* src = ei;
    const int* dst = ei + Ne;
    float* out = (float*)d_out;

    const int TB = 256;

    // CSR build + conv1 linear (merged)
    k_hist_lin1<<<HB + (Nn*64+TB-1)/TB, TB>>>(dst, ea, x, Wl1, bl1, Wr1, br1);
    k_scanprep<<<1, 1024>>>();
    k_scatter<<<(Ne+TB-1)/TB, TB>>>(src, dst, ea);

    // conv1 (low-rank aggregation) — one warp-block per node
    k_conv1lr<<<Nn, 32>>>(x, Wl1, bl1, We1, att1, bias1, g1, be1);

    // conv2
    k_gemm_dual<<<dim3(8, (Nn+63)/64), 256>>>(Wl2, bl2, Wr2, br2);
    k_conv2<<<Nn, 32>>>(We2, att2, bias2, g2, be2);

    // policy head (fused final projection)
    k_gemm_pol<<<(Nn+63)/64, 256>>>(Wp1, bp1, Wp2, bp2);

    // global softmax (two-phase)
    k_red1<<<NRED, 256>>>();
    k_out<<<(Nn*4+TB-1)/TB, TB>>>(out);
}